// round 5
// baseline (speedup 1.0000x reference)
#include <cuda_runtime.h>
#include <cuda_bf16.h>
#include <math.h>
#include <stdint.h>

#define N_ENT  50000
#define N_PAD  50048           // 391 * 128
#define N_EDGE 500000
#define H      128

// ================= scratch (static __device__) =================
__device__ int      g_deg[N_ENT];
__device__ int      g_off[N_ENT + 1];
__device__ int      g_cur[N_ENT];
__device__ unsigned g_pk[N_EDGE];                            // packed src*512 + rel_id
__device__ __align__(16) __nv_bfloat16 g_ahi[3][N_PAD * H];  // neigh hi (bf16)
__device__ __align__(16) __nv_bfloat16 g_alo[3][N_PAD * H];  // neigh lo (bf16)
__device__ __align__(16) __nv_bfloat16 g_wthi[3][H * H];     // W^T hi (h-major rows)
__device__ __align__(16) __nv_bfloat16 g_wtlo[3][H * H];     // W^T lo

// ================= helpers =================
__device__ __forceinline__ float dot4(float4 a, float4 b) {
    return a.x * b.x + a.y * b.y + a.z * b.z + a.w * b.w;
}
__device__ __forceinline__ float fast_tanh(float x) {
    float e = __expf(2.f * x);
    return 1.f - __fdividef(2.f, e + 1.f);
}
__device__ __forceinline__ uint32_t smem_u32(const void* p) {
    uint32_t a;
    asm("{ .reg .u64 t; cvta.to.shared.u64 t, %1; cvt.u32.u64 %0, t; }" : "=r"(a) : "l"(p));
    return a;
}
#define LDSM4(R0, R1, R2, R3, addr) \
    asm volatile("ldmatrix.sync.aligned.m8n8.x4.shared.b16 {%0,%1,%2,%3}, [%4];" \
        : "=r"(R0), "=r"(R1), "=r"(R2), "=r"(R3) : "r"(addr))
#define MMA16816(C, A0, A1, A2, A3, B0, B1) \
    asm volatile("mma.sync.aligned.m16n8k16.row.col.f32.bf16.bf16.f32 " \
        "{%0,%1,%2,%3}, {%4,%5,%6,%7}, {%8,%9}, {%0,%1,%2,%3};" \
        : "+f"((C)[0]), "+f"((C)[1]), "+f"((C)[2]), "+f"((C)[3]) \
        : "r"(A0), "r"(A1), "r"(A2), "r"(A3), "r"(B0), "r"(B1))
#define CP16(sm_addr, gptr) \
    asm volatile("cp.async.cg.shared.global [%0], [%1], 16;" :: "r"(sm_addr), "l"(gptr))
#define CP_COMMIT() asm volatile("cp.async.commit_group;")
#define CP_WAIT0()  asm volatile("cp.async.wait_group 0;")

// ================= K0: copy ent -> out, zero degree, zero A-pad rows ======
__global__ void k_init(const float* __restrict__ ent, float* __restrict__ out) {
    int i = blockIdx.x * blockDim.x + threadIdx.x;
    out[i] = ent[i];
    if (i < N_ENT) g_deg[i] = 0;
    if (i < 3 * (N_PAD - N_ENT) * H) {
        int l = i / ((N_PAD - N_ENT) * H);
        int r = i % ((N_PAD - N_ENT) * H);
        g_ahi[l][N_ENT * H + r] = __float2bfloat16(0.f);
        g_alo[l][N_ENT * H + r] = __float2bfloat16(0.f);
    }
}

// ================= K1: degree histogram =================
__global__ void k_hist(const int* __restrict__ dst) {
    int e = blockIdx.x * blockDim.x + threadIdx.x;
    if (e < N_EDGE) atomicAdd(&g_deg[dst[e]], 1);
}

// ================= K2: single-block exclusive scan =================
__global__ void k_scan() {
    __shared__ int part[1024];
    const int CH = (N_ENT + 1023) / 1024;
    int t = threadIdx.x;
    int begin = t * CH;
    int end = begin + CH < N_ENT ? begin + CH : N_ENT;
    int s = 0;
    for (int i = begin; i < end; i++) s += g_deg[i];
    part[t] = s;
    __syncthreads();
    #pragma unroll
    for (int o = 1; o < 1024; o <<= 1) {
        int v = (t >= o) ? part[t - o] : 0;
        __syncthreads();
        part[t] += v;
        __syncthreads();
    }
    int run = (t == 0) ? 0 : part[t - 1];
    for (int i = begin; i < end; i++) {
        g_off[i] = run;
        g_cur[i] = run;
        run += g_deg[i];
    }
    if (t == 1023) g_off[N_ENT] = run;
}

// ================= K3: dst-grouped edge lists =================
__global__ void k_fill(const int* __restrict__ src, const int* __restrict__ dst,
                       const int* __restrict__ rid) {
    int e = blockIdx.x * blockDim.x + threadIdx.x;
    if (e >= N_EDGE) return;
    int p = atomicAdd(&g_cur[dst[e]], 1);
    g_pk[p] = (unsigned)src[e] * 512u + (unsigned)rid[e];
}

// ================= K4: W^T + bf16 hi/lo split =================
__global__ void k_wprep(const float* __restrict__ we, const float* __restrict__ wn,
                        const float* __restrict__ wc) {
    int i = blockIdx.x * blockDim.x + threadIdx.x;   // 3*16384
    int l = i >> 14, r = i & 16383;
    int k = r >> 7, h = r & 127;
    const float* W = (l == 0) ? we : (l == 1) ? wn : wc;
    float x = W[k * H + h];
    __nv_bfloat16 hi = __float2bfloat16(x);
    g_wthi[l][h * H + k] = hi;
    g_wtlo[l][h * H + k] = __float2bfloat16(x - __bfloat162float(hi));
}

// ================= K5: warp-per-node fused agg (4-edge ILP) ==============
__device__ __forceinline__ void split_store4(__nv_bfloat16* hip, __nv_bfloat16* lop,
                                             float a, float b, float c, float d) {
    __nv_bfloat162 h01 = __floats2bfloat162_rn(a, b);
    __nv_bfloat162 h23 = __floats2bfloat162_rn(c, d);
    __nv_bfloat162 l01 = __floats2bfloat162_rn(a - __bfloat162float(h01.x),
                                               b - __bfloat162float(h01.y));
    __nv_bfloat162 l23 = __floats2bfloat162_rn(c - __bfloat162float(h23.x),
                                               d - __bfloat162float(h23.y));
    *(__nv_bfloat162*)(hip)     = h01;
    *(__nv_bfloat162*)(hip + 2) = h23;
    *(__nv_bfloat162*)(lop)     = l01;
    *(__nv_bfloat162*)(lop + 2) = l23;
}

__global__ void __launch_bounds__(256)
k_agg(const float* __restrict__ ent, const float* __restrict__ rel) {
    int w    = (blockIdx.x * blockDim.x + threadIdx.x) >> 5;
    int lane = threadIdx.x & 31;
    if (w >= N_ENT) return;

    float4 v = ((const float4*)(ent + (size_t)w * H))[lane];
    int start = g_off[w], end = g_off[w + 1];

    float4 a0 = make_float4(0.f, 0.f, 0.f, 0.f), a1 = a0, a2 = a0;
    float s0 = 0.f, s1 = 0.f, s2 = 0.f;

    for (int i = start; i < end; i += 4) {
        unsigned pk[4];
        float4 u[4], q[4];
        #pragma unroll
        for (int j = 0; j < 4; j++) {
            int idx = i + j;
            if (idx >= end) idx = end - 1;       // clamp; masked below
            pk[j] = g_pk[idx];
        }
        #pragma unroll
        for (int j = 0; j < 4; j++) {
            u[j] = ((const float4*)(ent + (size_t)(pk[j] >> 9) * H))[lane];
            q[j] = ((const float4*)(rel + (size_t)(pk[j] & 511u) * H))[lane];
        }
        float dn[4], de[4];
        #pragma unroll
        for (int j = 0; j < 4; j++) {
            dn[j] = dot4(u[j], v);
            de[j] = dot4(q[j], v);
        }
        #pragma unroll
        for (int o = 16; o; o >>= 1) {
            #pragma unroll
            for (int j = 0; j < 4; j++) {
                dn[j] += __shfl_xor_sync(0xffffffffu, dn[j], o);
                de[j] += __shfl_xor_sync(0xffffffffu, de[j], o);
            }
        }
        #pragma unroll
        for (int j = 0; j < 4; j++) {
            if (i + j < end) {
                float ee = __expf(de[j]), en = __expf(dn[j]), ec = ee * en;
                s0 += ee; s1 += en; s2 += ec;
                a0.x += ee * q[j].x; a0.y += ee * q[j].y;
                a0.z += ee * q[j].z; a0.w += ee * q[j].w;
                a1.x += en * u[j].x; a1.y += en * u[j].y;
                a1.z += en * u[j].z; a1.w += en * u[j].w;
                a2.x += ec * (u[j].x + q[j].x); a2.y += ec * (u[j].y + q[j].y);
                a2.z += ec * (u[j].z + q[j].z); a2.w += ec * (u[j].w + q[j].w);
            }
        }
    }

    float i0 = (end > start) ? 1.f / s0 : 0.f;
    float i1 = (end > start) ? 1.f / s1 : 0.f;
    float i2 = (end > start) ? 1.f / s2 : 0.f;
    size_t off = (size_t)w * H + lane * 4;
    split_store4(&g_ahi[0][off], &g_alo[0][off], a0.x * i0, a0.y * i0, a0.z * i0, a0.w * i0);
    split_store4(&g_ahi[1][off], &g_alo[1][off], a1.x * i1, a1.y * i1, a1.z * i1, a1.w * i1);
    split_store4(&g_ahi[2][off], &g_alo[2][off], a2.x * i2, a2.y * i2, a2.z * i2, a2.w * i2);
}

// ================= K6: HMMA split-bf16 GEMM ===============================
// CTA = (row-tile, N-half). 128 rows x 64 cols, loops 3 layers internally.
// smem: A hi/lo (128 x 272B) + W-half hi/lo (64 x 272B) = 102 KB -> 2 CTA/SM
#define PITCH    272
#define A_TILE_B (128 * PITCH)          // 34816
#define W_TILE_B (64 * PITCH)           // 17408
#define SM_AH    0
#define SM_AL    A_TILE_B
#define SM_WH    (2 * A_TILE_B)
#define SM_WL    (2 * A_TILE_B + W_TILE_B)
#define SM_TOT   (2 * A_TILE_B + 2 * W_TILE_B)   // 104448

__global__ void __launch_bounds__(256, 2)
k_gemm3(float* __restrict__ out) {
    extern __shared__ char sm[];
    uint32_t sb = smem_u32(sm);
    int tid  = threadIdx.x;
    int wid  = tid >> 5;
    int lane = tid & 31;
    int tile = blockIdx.x >> 1;
    int half = blockIdx.x & 1;
    int row0 = tile * 128;

    // lane-dependent ldmatrix base offsets
    int q = lane >> 3, r = lane & 7;
    uint32_t a_off = (uint32_t)((wid * 16 + r + (q & 1) * 8) * PITCH + (q >> 1) * 16);
    uint32_t b_off = (uint32_t)(((q >> 1) * 8 + r) * PITCH + (q & 1) * 16);

    for (int layer = 0; layer < 3; layer++) {
        const uint4* ah = (const uint4*)(g_ahi[layer] + (size_t)row0 * H);
        const uint4* al = (const uint4*)(g_alo[layer] + (size_t)row0 * H);
        const uint4* wh = (const uint4*)(g_wthi[layer]) + half * 64 * 16;
        const uint4* wl = (const uint4*)(g_wtlo[layer]) + half * 64 * 16;

        // A tiles: 2048 uint4 each -> 8 per thread per tile
        #pragma unroll
        for (int i = 0; i < 8; i++) {
            int idx = i * 256 + tid;            // 0..2047
            int row = idx >> 4, ch = idx & 15;
            uint32_t so = (uint32_t)(row * PITCH + ch * 16);
            CP16(sb + SM_AH + so, ah + row * 16 + ch);
            CP16(sb + SM_AL + so, al + row * 16 + ch);
        }
        // W half tiles: 1024 uint4 each -> 4 per thread per tile
        #pragma unroll
        for (int i = 0; i < 4; i++) {
            int idx = i * 256 + tid;            // 0..1023
            int row = idx >> 4, ch = idx & 15;
            uint32_t so = (uint32_t)(row * PITCH + ch * 16);
            CP16(sb + SM_WH + so, wh + row * 16 + ch);
            CP16(sb + SM_WL + so, wl + row * 16 + ch);
        }
        CP_COMMIT();
        CP_WAIT0();
        __syncthreads();

        // ---- 3 passes (AhBh, AhBl, AlBh) into fp32 acc ----
        float c[8][4];
        #pragma unroll
        for (int nt = 0; nt < 8; nt++)
            #pragma unroll
            for (int j = 0; j < 4; j++) c[nt][j] = 0.f;

        #pragma unroll
        for (int pass = 0; pass < 3; pass++) {
            uint32_t ab = sb + (pass == 2 ? SM_AL : SM_AH) + a_off;
            uint32_t bb = sb + (pass == 1 ? SM_WL : SM_WH) + b_off;
            #pragma unroll
            for (int ks = 0; ks < 8; ks++) {
                uint32_t aa0, aa1, aa2, aa3;
                LDSM4(aa0, aa1, aa2, aa3, ab + ks * 32);
                #pragma unroll
                for (int np = 0; np < 4; np++) {
                    uint32_t b0, b1, b2, b3;
                    LDSM4(b0, b1, b2, b3, bb + np * (16 * PITCH) + ks * 32);
                    MMA16816(c[np * 2],     aa0, aa1, aa2, aa3, b0, b1);
                    MMA16816(c[np * 2 + 1], aa0, aa1, aa2, aa3, b2, b3);
                }
            }
        }

        // ---- epilogue: out += tanh(c); this CTA owns (rows, col-half) ----
        int m0 = row0 + wid * 16 + (lane >> 2);
        int nb = (lane & 3) * 2;
        #pragma unroll
        for (int nt = 0; nt < 8; nt++) {
            int n = half * 64 + nt * 8 + nb;
            if (m0 < N_ENT) {
                float2* p = (float2*)(out + (size_t)m0 * H + n);
                float2 v0 = *p;
                v0.x += fast_tanh(c[nt][0]);
                v0.y += fast_tanh(c[nt][1]);
                *p = v0;
            }
            if (m0 + 8 < N_ENT) {
                float2* p = (float2*)(out + (size_t)(m0 + 8) * H + n);
                float2 v1 = *p;
                v1.x += fast_tanh(c[nt][2]);
                v1.y += fast_tanh(c[nt][3]);
                *p = v1;
            }
        }
        __syncthreads();    // before next layer overwrites smem
    }
}

// ================= launch =================
extern "C" void kernel_launch(void* const* d_in, const int* in_sizes, int n_in,
                              void* d_out, int out_size) {
    const float* ent    = (const float*)d_in[0];
    const float* rel    = (const float*)d_in[1];
    const float* w_edge = (const float*)d_in[2];
    const float* w_node = (const float*)d_in[3];
    const float* w_comp = (const float*)d_in[4];
    const int*   src    = (const int*)d_in[5];
    const int*   dst    = (const int*)d_in[6];
    const int*   rid    = (const int*)d_in[7];
    float*       out    = (float*)d_out;

    cudaFuncSetAttribute(k_gemm3, cudaFuncAttributeMaxDynamicSharedMemorySize, SM_TOT);

    k_init <<<(N_ENT * H) / 256, 256>>>(ent, out);
    k_hist <<<(N_EDGE + 255) / 256, 256>>>(dst);
    k_scan <<<1, 1024>>>();
    k_fill <<<(N_EDGE + 255) / 256, 256>>>(src, dst, rid);
    k_wprep<<<(3 * H * H) / 256, 256>>>(w_edge, w_node, w_comp);
    k_agg  <<<N_ENT / 8, 256>>>(ent, rel);

    k_gemm3<<<(N_PAD / 128) * 2, 256, SM_TOT>>>(out);   // 782 CTAs
}

// round 6
// speedup vs baseline: 1.3188x; 1.3188x over previous
#include <cuda_runtime.h>
#include <cuda_fp16.h>
#include <math.h>
#include <stdint.h>

#define N_ENT  50000
#define N_PAD  50048           // 391 * 128
#define N_EDGE 500000
#define H      128

// ================= scratch (static __device__) =================
__device__ int      g_deg[N_ENT];
__device__ int      g_off[N_ENT + 1];
__device__ int      g_cur[N_ENT];
__device__ unsigned g_pk[N_EDGE];                        // packed src*512 + rel_id
__device__ __align__(16) __half g_a[3][N_PAD * H];       // neigh (fp16)
__device__ __align__(16) __half g_wt[3][H * H];          // W^T (fp16, h-major rows)

// ================= helpers =================
__device__ __forceinline__ float dot4(float4 a, float4 b) {
    return a.x * b.x + a.y * b.y + a.z * b.z + a.w * b.w;
}
__device__ __forceinline__ float fast_tanh(float x) {
    float e = __expf(2.f * x);
    return 1.f - __fdividef(2.f, e + 1.f);
}
__device__ __forceinline__ uint32_t smem_u32(const void* p) {
    uint32_t a;
    asm("{ .reg .u64 t; cvta.to.shared.u64 t, %1; cvt.u32.u64 %0, t; }" : "=r"(a) : "l"(p));
    return a;
}
#define LDSM4(R0, R1, R2, R3, addr) \
    asm volatile("ldmatrix.sync.aligned.m8n8.x4.shared.b16 {%0,%1,%2,%3}, [%4];" \
        : "=r"(R0), "=r"(R1), "=r"(R2), "=r"(R3) : "r"(addr))
#define MMA16816(C, A0, A1, A2, A3, B0, B1) \
    asm volatile("mma.sync.aligned.m16n8k16.row.col.f32.f16.f16.f32 " \
        "{%0,%1,%2,%3}, {%4,%5,%6,%7}, {%8,%9}, {%0,%1,%2,%3};" \
        : "+f"((C)[0]), "+f"((C)[1]), "+f"((C)[2]), "+f"((C)[3]) \
        : "r"(A0), "r"(A1), "r"(A2), "r"(A3), "r"(B0), "r"(B1))

// ================= K0: copy ent -> out, zero degree, zero A-pad rows ======
__global__ void k_init(const float* __restrict__ ent, float* __restrict__ out) {
    int i = blockIdx.x * blockDim.x + threadIdx.x;
    out[i] = ent[i];
    if (i < N_ENT) g_deg[i] = 0;
    if (i < 3 * (N_PAD - N_ENT) * H) {                   // 18432 pad elems
        int l = i / ((N_PAD - N_ENT) * H);
        int r = i % ((N_PAD - N_ENT) * H);
        g_a[l][N_ENT * H + r] = __float2half(0.f);
    }
}

// ================= K1: degree histogram =================
__global__ void k_hist(const int* __restrict__ dst) {
    int e = blockIdx.x * blockDim.x + threadIdx.x;
    if (e < N_EDGE) atomicAdd(&g_deg[dst[e]], 1);
}

// ================= K2: single-block exclusive scan =================
__global__ void k_scan() {
    __shared__ int part[1024];
    const int CH = (N_ENT + 1023) / 1024;
    int t = threadIdx.x;
    int begin = t * CH;
    int end = begin + CH < N_ENT ? begin + CH : N_ENT;
    int s = 0;
    for (int i = begin; i < end; i++) s += g_deg[i];
    part[t] = s;
    __syncthreads();
    #pragma unroll
    for (int o = 1; o < 1024; o <<= 1) {
        int v = (t >= o) ? part[t - o] : 0;
        __syncthreads();
        part[t] += v;
        __syncthreads();
    }
    int run = (t == 0) ? 0 : part[t - 1];
    for (int i = begin; i < end; i++) {
        g_off[i] = run;
        g_cur[i] = run;
        run += g_deg[i];
    }
    if (t == 1023) g_off[N_ENT] = run;
}

// ================= K3: dst-grouped edge lists =================
__global__ void k_fill(const int* __restrict__ src, const int* __restrict__ dst,
                       const int* __restrict__ rid) {
    int e = blockIdx.x * blockDim.x + threadIdx.x;
    if (e >= N_EDGE) return;
    int p = atomicAdd(&g_cur[dst[e]], 1);
    g_pk[p] = (unsigned)src[e] * 512u + (unsigned)rid[e];
}

// ================= K4: W^T -> fp16 =================
__global__ void k_wprep(const float* __restrict__ we, const float* __restrict__ wn,
                        const float* __restrict__ wc) {
    int i = blockIdx.x * blockDim.x + threadIdx.x;   // 3*16384
    int l = i >> 14, r = i & 16383;
    int k = r >> 7, h = r & 127;
    const float* W = (l == 0) ? we : (l == 1) ? wn : wc;
    g_wt[l][h * H + k] = __float2half(W[k * H + h]);
}

// ================= K5: warp-per-node fused agg (R4 2-edge form) ==========
__global__ void __launch_bounds__(256)
k_agg(const float* __restrict__ ent, const float* __restrict__ rel) {
    int w    = (blockIdx.x * blockDim.x + threadIdx.x) >> 5;
    int lane = threadIdx.x & 31;
    if (w >= N_ENT) return;

    float4 v = ((const float4*)(ent + (size_t)w * H))[lane];
    int start = g_off[w], end = g_off[w + 1];

    float4 a0 = make_float4(0.f, 0.f, 0.f, 0.f), a1 = a0, a2 = a0;
    float s0 = 0.f, s1 = 0.f, s2 = 0.f;

    for (int i = start; i < end; i += 2) {
        unsigned pA = g_pk[i];
        int hasB    = (i + 1 < end);
        unsigned pB = g_pk[hasB ? i + 1 : i];

        float4 uA = ((const float4*)(ent + (size_t)(pA >> 9) * H))[lane];
        float4 qA = ((const float4*)(rel + (size_t)(pA & 511u) * H))[lane];
        float4 uB = ((const float4*)(ent + (size_t)(pB >> 9) * H))[lane];
        float4 qB = ((const float4*)(rel + (size_t)(pB & 511u) * H))[lane];

        float dnA = dot4(uA, v), deA = dot4(qA, v);
        float dnB = dot4(uB, v), deB = dot4(qB, v);
        #pragma unroll
        for (int o = 16; o; o >>= 1) {
            dnA += __shfl_xor_sync(0xffffffffu, dnA, o);
            deA += __shfl_xor_sync(0xffffffffu, deA, o);
            dnB += __shfl_xor_sync(0xffffffffu, dnB, o);
            deB += __shfl_xor_sync(0xffffffffu, deB, o);
        }
        float eA = __expf(deA), nA = __expf(dnA), cA = eA * nA;
        s0 += eA; s1 += nA; s2 += cA;
        a0.x += eA * qA.x; a0.y += eA * qA.y; a0.z += eA * qA.z; a0.w += eA * qA.w;
        a1.x += nA * uA.x; a1.y += nA * uA.y; a1.z += nA * uA.z; a1.w += nA * uA.w;
        a2.x += cA * (uA.x + qA.x); a2.y += cA * (uA.y + qA.y);
        a2.z += cA * (uA.z + qA.z); a2.w += cA * (uA.w + qA.w);
        if (hasB) {
            float eB = __expf(deB), nB = __expf(dnB), cB = eB * nB;
            s0 += eB; s1 += nB; s2 += cB;
            a0.x += eB * qB.x; a0.y += eB * qB.y; a0.z += eB * qB.z; a0.w += eB * qB.w;
            a1.x += nB * uB.x; a1.y += nB * uB.y; a1.z += nB * uB.z; a1.w += nB * uB.w;
            a2.x += cB * (uB.x + qB.x); a2.y += cB * (uB.y + qB.y);
            a2.z += cB * (uB.z + qB.z); a2.w += cB * (uB.w + qB.w);
        }
    }

    float i0 = (end > start) ? 1.f / s0 : 0.f;
    float i1 = (end > start) ? 1.f / s1 : 0.f;
    float i2 = (end > start) ? 1.f / s2 : 0.f;
    size_t off = (size_t)w * H + lane * 4;
    *(__half2*)&g_a[0][off]     = __floats2half2_rn(a0.x * i0, a0.y * i0);
    *(__half2*)&g_a[0][off + 2] = __floats2half2_rn(a0.z * i0, a0.w * i0);
    *(__half2*)&g_a[1][off]     = __floats2half2_rn(a1.x * i1, a1.y * i1);
    *(__half2*)&g_a[1][off + 2] = __floats2half2_rn(a1.z * i1, a1.w * i1);
    *(__half2*)&g_a[2][off]     = __floats2half2_rn(a2.x * i2, a2.y * i2);
    *(__half2*)&g_a[2][off + 2] = __floats2half2_rn(a2.z * i2, a2.w * i2);
}

// ================= K6: fp16 HMMA GEMM, 128x128/CTA, 3 layers, 1 pass =====
// smem: A tile + W tile, 128 rows x 272B pitch each = 68 KB -> 2 CTA/SM
#define PITCH    272
#define TILE_B   (128 * PITCH)          // 34816
#define SM_A     0
#define SM_W     TILE_B
#define SM_TOT   (2 * TILE_B)           // 69632

__global__ void __launch_bounds__(256, 2)
k_gemm3(float* __restrict__ out) {
    extern __shared__ char sm[];
    uint32_t sb = smem_u32(sm);
    int tid  = threadIdx.x;
    int wid  = tid >> 5;
    int lane = tid & 31;
    int row0 = blockIdx.x * 128;

    // lane-dependent ldmatrix base offsets (q = lane>>3, r = lane&7)
    int q = lane >> 3, r = lane & 7;
    uint32_t a_off = (uint32_t)((wid * 16 + r + (q & 1) * 8) * PITCH + (q >> 1) * 16);
    uint32_t b_off = (uint32_t)(((q >> 1) * 8 + r) * PITCH + (q & 1) * 16);

    for (int layer = 0; layer < 3; layer++) {
        const uint4* ap = (const uint4*)(g_a[layer] + (size_t)row0 * H);
        const uint4* wp = (const uint4*)(g_wt[layer]);
        #pragma unroll
        for (int i = 0; i < 8; i++) {
            int idx = i * 256 + tid;            // 0..2047
            int row = idx >> 4, ch = idx & 15;
            uint32_t so = (uint32_t)(row * PITCH + ch * 16);
            uint4 va = ap[row * 16 + ch];
            uint4 vb = wp[row * 16 + ch];
            *(uint4*)(sm + SM_A + so) = va;
            *(uint4*)(sm + SM_W + so) = vb;
        }
        __syncthreads();

        float c[16][4];
        #pragma unroll
        for (int nt = 0; nt < 16; nt++)
            #pragma unroll
            for (int j = 0; j < 4; j++) c[nt][j] = 0.f;

        uint32_t ab = sb + SM_A + a_off;
        uint32_t bb = sb + SM_W + b_off;
        #pragma unroll
        for (int ks = 0; ks < 8; ks++) {
            uint32_t aa0, aa1, aa2, aa3;
            LDSM4(aa0, aa1, aa2, aa3, ab + ks * 32);
            #pragma unroll
            for (int np = 0; np < 8; np++) {
                uint32_t b0, b1, b2, b3;
                LDSM4(b0, b1, b2, b3, bb + np * (16 * PITCH) + ks * 32);
                MMA16816(c[np * 2],     aa0, aa1, aa2, aa3, b0, b1);
                MMA16816(c[np * 2 + 1], aa0, aa1, aa2, aa3, b2, b3);
            }
        }

        // ---- epilogue: out += tanh(c); CTA owns rows, layers serialized ----
        int m0 = row0 + wid * 16 + (lane >> 2);
        int nb = (lane & 3) * 2;
        #pragma unroll
        for (int nt = 0; nt < 16; nt++) {
            int n = nt * 8 + nb;
            if (m0 < N_ENT) {
                float2* p = (float2*)(out + (size_t)m0 * H + n);
                float2 v0 = *p;
                v0.x += fast_tanh(c[nt][0]);
                v0.y += fast_tanh(c[nt][1]);
                *p = v0;
            }
            if (m0 + 8 < N_ENT) {
                float2* p = (float2*)(out + (size_t)(m0 + 8) * H + n);
                float2 v1 = *p;
                v1.x += fast_tanh(c[nt][2]);
                v1.y += fast_tanh(c[nt][3]);
                *p = v1;
            }
        }
        __syncthreads();    // before next layer overwrites smem
    }
}

// ================= launch =================
extern "C" void kernel_launch(void* const* d_in, const int* in_sizes, int n_in,
                              void* d_out, int out_size) {
    const float* ent    = (const float*)d_in[0];
    const float* rel    = (const float*)d_in[1];
    const float* w_edge = (const float*)d_in[2];
    const float* w_node = (const float*)d_in[3];
    const float* w_comp = (const float*)d_in[4];
    const int*   src    = (const int*)d_in[5];
    const int*   dst    = (const int*)d_in[6];
    const int*   rid    = (const int*)d_in[7];
    float*       out    = (float*)d_out;

    cudaFuncSetAttribute(k_gemm3, cudaFuncAttributeMaxDynamicSharedMemorySize, SM_TOT);

    k_init <<<(N_ENT * H) / 256, 256>>>(ent, out);
    k_hist <<<(N_EDGE + 255) / 256, 256>>>(dst);
    k_scan <<<1, 1024>>>();
    k_fill <<<(N_EDGE + 255) / 256, 256>>>(src, dst, rid);
    k_wprep<<<(3 * H * H) / 256, 256>>>(w_edge, w_node, w_comp);
    k_agg  <<<N_ENT / 8, 256>>>(ent, rel);

    k_gemm3<<<N_PAD / 128, 256, SM_TOT>>>(out);   // 391 CTAs, 2/SM resident
}

// round 7
// speedup vs baseline: 1.4965x; 1.1348x over previous
#include <cuda_runtime.h>
#include <cuda_fp16.h>
#include <math.h>
#include <stdint.h>

#define N_ENT  50000
#define N_PAD  50048           // 391 * 128
#define N_EDGE 500000
#define H      128

// ================= scratch (static __device__, zero-init at load) =========
__device__ int      g_deg[N_ENT];        // re-zeroed by k_wprep each call
__device__ int      g_off[N_ENT + 1];
__device__ int      g_cur[N_ENT];
__device__ unsigned g_pk[N_EDGE];        // packed src*512 + rel_id
__device__ __align__(16) __half g_a[3][N_PAD * H];   // neigh fp16 (pad rows stay 0)
__device__ __align__(16) __half g_wt[3][H * H];      // W^T fp16 (h-major rows)

// ================= helpers =================
__device__ __forceinline__ float dot4(float4 a, float4 b) {
    return a.x * b.x + a.y * b.y + a.z * b.z + a.w * b.w;
}
__device__ __forceinline__ float fast_tanh(float x) {
    float e = __expf(2.f * x);
    return 1.f - __fdividef(2.f, e + 1.f);
}
__device__ __forceinline__ uint32_t smem_u32(const void* p) {
    uint32_t a;
    asm("{ .reg .u64 t; cvta.to.shared.u64 t, %1; cvt.u32.u64 %0, t; }" : "=r"(a) : "l"(p));
    return a;
}
#define LDSM4(R0, R1, R2, R3, addr) \
    asm volatile("ldmatrix.sync.aligned.m8n8.x4.shared.b16 {%0,%1,%2,%3}, [%4];" \
        : "=r"(R0), "=r"(R1), "=r"(R2), "=r"(R3) : "r"(addr))
#define MMA16816(C, A0, A1, A2, A3, B0, B1) \
    asm volatile("mma.sync.aligned.m16n8k16.row.col.f32.f16.f16.f32 " \
        "{%0,%1,%2,%3}, {%4,%5,%6,%7}, {%8,%9}, {%0,%1,%2,%3};" \
        : "+f"((C)[0]), "+f"((C)[1]), "+f"((C)[2]), "+f"((C)[3]) \
        : "r"(A0), "r"(A1), "r"(A2), "r"(A3), "r"(B0), "r"(B1))

// ================= K1: degree histogram (g_deg pre-zeroed) ===============
__global__ void k_hist(const int* __restrict__ dst) {
    int e = blockIdx.x * blockDim.x + threadIdx.x;
    if (e < N_EDGE) atomicAdd(&g_deg[dst[e]], 1);
}

// ================= K2: single-block exclusive scan =================
__global__ void k_scan() {
    __shared__ int part[1024];
    const int CH = (N_ENT + 1023) / 1024;
    int t = threadIdx.x;
    int begin = t * CH;
    int end = begin + CH < N_ENT ? begin + CH : N_ENT;
    int s = 0;
    for (int i = begin; i < end; i++) s += g_deg[i];
    part[t] = s;
    __syncthreads();
    #pragma unroll
    for (int o = 1; o < 1024; o <<= 1) {
        int v = (t >= o) ? part[t - o] : 0;
        __syncthreads();
        part[t] += v;
        __syncthreads();
    }
    int run = (t == 0) ? 0 : part[t - 1];
    for (int i = begin; i < end; i++) {
        g_off[i] = run;
        g_cur[i] = run;
        run += g_deg[i];
    }
    if (t == 1023) g_off[N_ENT] = run;
}

// ================= K3: dst-grouped edge lists =================
__global__ void k_fill(const int* __restrict__ src, const int* __restrict__ dst,
                       const int* __restrict__ rid) {
    int e = blockIdx.x * blockDim.x + threadIdx.x;
    if (e >= N_EDGE) return;
    int p = atomicAdd(&g_cur[dst[e]], 1);
    g_pk[p] = (unsigned)src[e] * 512u + (unsigned)rid[e];
}

// ================= K4: warp-per-node fused agg (pk software-pipelined) ====
__global__ void __launch_bounds__(256)
k_agg(const float* __restrict__ ent, const float* __restrict__ rel) {
    int w    = (blockIdx.x * blockDim.x + threadIdx.x) >> 5;
    int lane = threadIdx.x & 31;
    if (w >= N_ENT) return;

    float4 v = ((const float4*)(ent + (size_t)w * H))[lane];
    int start = g_off[w], end = g_off[w + 1];

    float4 a0 = make_float4(0.f, 0.f, 0.f, 0.f), a1 = a0, a2 = a0;
    float s0 = 0.f, s1 = 0.f, s2 = 0.f;

    // pk prefetch: next pair issued at loop top, overlapping current gathers
    unsigned nA = 0, nB = 0;
    if (start < end) {
        nA = g_pk[start];
        nB = (start + 1 < end) ? g_pk[start + 1] : nA;
    }
    for (int i = start; i < end; i += 2) {
        unsigned pA = nA, pB = nB;
        int hasB = (i + 1 < end);
        int j = i + 2;
        if (j < end) {
            nA = g_pk[j];
            nB = (j + 1 < end) ? g_pk[j + 1] : nA;
        }

        float4 uA = ((const float4*)(ent + (size_t)(pA >> 9) * H))[lane];
        float4 qA = ((const float4*)(rel + (size_t)(pA & 511u) * H))[lane];
        float4 uB = ((const float4*)(ent + (size_t)(pB >> 9) * H))[lane];
        float4 qB = ((const float4*)(rel + (size_t)(pB & 511u) * H))[lane];

        float dnA = dot4(uA, v), deA = dot4(qA, v);
        float dnB = dot4(uB, v), deB = dot4(qB, v);
        #pragma unroll
        for (int o = 16; o; o >>= 1) {
            dnA += __shfl_xor_sync(0xffffffffu, dnA, o);
            deA += __shfl_xor_sync(0xffffffffu, deA, o);
            dnB += __shfl_xor_sync(0xffffffffu, dnB, o);
            deB += __shfl_xor_sync(0xffffffffu, deB, o);
        }
        float eA = __expf(deA), nAx = __expf(dnA), cA = eA * nAx;
        s0 += eA; s1 += nAx; s2 += cA;
        a0.x += eA * qA.x; a0.y += eA * qA.y; a0.z += eA * qA.z; a0.w += eA * qA.w;
        a1.x += nAx * uA.x; a1.y += nAx * uA.y; a1.z += nAx * uA.z; a1.w += nAx * uA.w;
        a2.x += cA * (uA.x + qA.x); a2.y += cA * (uA.y + qA.y);
        a2.z += cA * (uA.z + qA.z); a2.w += cA * (uA.w + qA.w);
        if (hasB) {
            float eB = __expf(deB), nBx = __expf(dnB), cB = eB * nBx;
            s0 += eB; s1 += nBx; s2 += cB;
            a0.x += eB * qB.x; a0.y += eB * qB.y; a0.z += eB * qB.z; a0.w += eB * qB.w;
            a1.x += nBx * uB.x; a1.y += nBx * uB.y; a1.z += nBx * uB.z; a1.w += nBx * uB.w;
            a2.x += cB * (uB.x + qB.x); a2.y += cB * (uB.y + qB.y);
            a2.z += cB * (uB.z + qB.z); a2.w += cB * (uB.w + qB.w);
        }
    }

    float i0 = (end > start) ? 1.f / s0 : 0.f;
    float i1 = (end > start) ? 1.f / s1 : 0.f;
    float i2 = (end > start) ? 1.f / s2 : 0.f;
    size_t off = (size_t)w * H + lane * 4;
    *(__half2*)&g_a[0][off]     = __floats2half2_rn(a0.x * i0, a0.y * i0);
    *(__half2*)&g_a[0][off + 2] = __floats2half2_rn(a0.z * i0, a0.w * i0);
    *(__half2*)&g_a[1][off]     = __floats2half2_rn(a1.x * i1, a1.y * i1);
    *(__half2*)&g_a[1][off + 2] = __floats2half2_rn(a1.z * i1, a1.w * i1);
    *(__half2*)&g_a[2][off]     = __floats2half2_rn(a2.x * i2, a2.y * i2);
    *(__half2*)&g_a[2][off + 2] = __floats2half2_rn(a2.z * i2, a2.w * i2);
}

// ================= K5: W^T -> fp16  +  re-zero g_deg for next call ========
__global__ void k_wprep(const float* __restrict__ we, const float* __restrict__ wn,
                        const float* __restrict__ wc) {
    int i = blockIdx.x * blockDim.x + threadIdx.x;   // grid covers 50176
    if (i < 3 * H * H) {
        int l = i >> 14, r = i & 16383;
        int k = r >> 7, h = r & 127;
        const float* W = (l == 0) ? we : (l == 1) ? wn : wc;
        g_wt[l][h * H + k] = __float2half(W[k * H + h]);
    }
    if (i < N_ENT) g_deg[i] = 0;                     // g_deg dead after k_scan
}

// ================= K6: fp16 HMMA GEMM, 128x128/CTA, 3 layers ==============
// layer 0 epilogue: out = ent + tanh(c)  (replaces k_init's copy)
#define PITCH    272
#define TILE_B   (128 * PITCH)          // 34816
#define SM_A     0
#define SM_W     TILE_B
#define SM_TOT   (2 * TILE_B)           // 69632 -> 2 CTA/SM

__global__ void __launch_bounds__(256, 2)
k_gemm3(const float* __restrict__ ent, float* __restrict__ out) {
    extern __shared__ char sm[];
    uint32_t sb = smem_u32(sm);
    int tid  = threadIdx.x;
    int wid  = tid >> 5;
    int lane = tid & 31;
    int row0 = blockIdx.x * 128;

    int q = lane >> 3, r = lane & 7;
    uint32_t a_off = (uint32_t)((wid * 16 + r + (q & 1) * 8) * PITCH + (q >> 1) * 16);
    uint32_t b_off = (uint32_t)(((q >> 1) * 8 + r) * PITCH + (q & 1) * 16);

    for (int layer = 0; layer < 3; layer++) {
        const uint4* ap = (const uint4*)(g_a[layer] + (size_t)row0 * H);
        const uint4* wp = (const uint4*)(g_wt[layer]);
        #pragma unroll
        for (int i = 0; i < 8; i++) {
            int idx = i * 256 + tid;
            int row = idx >> 4, ch = idx & 15;
            uint32_t so = (uint32_t)(row * PITCH + ch * 16);
            uint4 va = ap[row * 16 + ch];
            uint4 vb = wp[row * 16 + ch];
            *(uint4*)(sm + SM_A + so) = va;
            *(uint4*)(sm + SM_W + so) = vb;
        }
        __syncthreads();

        float c[16][4];
        #pragma unroll
        for (int nt = 0; nt < 16; nt++)
            #pragma unroll
            for (int j = 0; j < 4; j++) c[nt][j] = 0.f;

        uint32_t ab = sb + SM_A + a_off;
        uint32_t bb = sb + SM_W + b_off;
        #pragma unroll
        for (int ks = 0; ks < 8; ks++) {
            uint32_t aa0, aa1, aa2, aa3;
            LDSM4(aa0, aa1, aa2, aa3, ab + ks * 32);
            #pragma unroll
            for (int np = 0; np < 8; np++) {
                uint32_t b0, b1, b2, b3;
                LDSM4(b0, b1, b2, b3, bb + np * (16 * PITCH) + ks * 32);
                MMA16816(c[np * 2],     aa0, aa1, aa2, aa3, b0, b1);
                MMA16816(c[np * 2 + 1], aa0, aa1, aa2, aa3, b2, b3);
            }
        }

        // ---- epilogue (CTA owns its rows; layers serialized within CTA) ----
        int m0 = row0 + wid * 16 + (lane >> 2);
        int nb = (lane & 3) * 2;
        #pragma unroll
        for (int nt = 0; nt < 16; nt++) {
            int n = nt * 8 + nb;
            if (m0 < N_ENT) {
                float2* p = (float2*)(out + (size_t)m0 * H + n);
                float2 v0;
                if (layer == 0) {
                    const float2* ep = (const float2*)(ent + (size_t)m0 * H + n);
                    v0 = *ep;
                } else {
                    v0 = *p;
                }
                v0.x += fast_tanh(c[nt][0]);
                v0.y += fast_tanh(c[nt][1]);
                *p = v0;
            }
            if (m0 + 8 < N_ENT) {
                float2* p = (float2*)(out + (size_t)(m0 + 8) * H + n);
                float2 v1;
                if (layer == 0) {
                    const float2* ep = (const float2*)(ent + (size_t)(m0 + 8) * H + n);
                    v1 = *ep;
                } else {
                    v1 = *p;
                }
                v1.x += fast_tanh(c[nt][2]);
                v1.y += fast_tanh(c[nt][3]);
                *p = v1;
            }
        }
        __syncthreads();
    }
}

// ================= launch =================
extern "C" void kernel_launch(void* const* d_in, const int* in_sizes, int n_in,
                              void* d_out, int out_size) {
    const float* ent    = (const float*)d_in[0];
    const float* rel    = (const float*)d_in[1];
    const float* w_edge = (const float*)d_in[2];
    const float* w_node = (const float*)d_in[3];
    const float* w_comp = (const float*)d_in[4];
    const int*   src    = (const int*)d_in[5];
    const int*   dst    = (const int*)d_in[6];
    const int*   rid    = (const int*)d_in[7];
    float*       out    = (float*)d_out;

    cudaFuncSetAttribute(k_gemm3, cudaFuncAttributeMaxDynamicSharedMemorySize, SM_TOT);

    // g_deg is zero at module load and re-zeroed by k_wprep every call.
    k_hist <<<(N_EDGE + 255) / 256, 256>>>(dst);            // launch 1
    k_scan <<<1, 1024>>>();                                 // launch 2
    k_fill <<<(N_EDGE + 255) / 256, 256>>>(src, dst, rid);  // launch 3
    k_agg  <<<N_ENT / 8, 256>>>(ent, rel);                  // launch 4  <- profiled
    k_wprep<<<196, 256>>>(w_edge, w_node, w_comp);          // launch 5
    k_gemm3<<<N_PAD / 128, 256, SM_TOT>>>(ent, out);        // launch 6
}

// round 8
// speedup vs baseline: 2.2750x; 1.5201x over previous
#include <cuda_runtime.h>
#include <cuda_fp16.h>
#include <math.h>
#include <stdint.h>

#define N_ENT  50000
#define N_PAD  50048           // 391 * 128
#define N_EDGE 500000
#define H      128

// ================= scratch (static __device__, zero-init at load) =========
// g_deg and g_base are re-zeroed by k_gemm3 at the end of every call.
__device__ int      g_deg[N_ENT];
__device__ int      g_off[N_ENT];
__device__ int      g_cur[N_ENT];
__device__ int      g_base;
__device__ unsigned g_pk[N_EDGE];        // packed src*512 + rel_id
__device__ __align__(16) __half g_a[3][N_PAD * H];   // neigh fp16 (pad rows stay 0)
__device__ __align__(16) __half g_wt[3][H * H];      // W^T fp16 (h-major rows)

// ================= helpers =================
__device__ __forceinline__ float dot4(float4 a, float4 b) {
    return a.x * b.x + a.y * b.y + a.z * b.z + a.w * b.w;
}
__device__ __forceinline__ float fast_tanh(float x) {
    float e = __expf(2.f * x);
    return 1.f - __fdividef(2.f, e + 1.f);
}
__device__ __forceinline__ uint32_t smem_u32(const void* p) {
    uint32_t a;
    asm("{ .reg .u64 t; cvta.to.shared.u64 t, %1; cvt.u32.u64 %0, t; }" : "=r"(a) : "l"(p));
    return a;
}
#define LDSM4(R0, R1, R2, R3, addr) \
    asm volatile("ldmatrix.sync.aligned.m8n8.x4.shared.b16 {%0,%1,%2,%3}, [%4];" \
        : "=r"(R0), "=r"(R1), "=r"(R2), "=r"(R3) : "r"(addr))
#define MMA16816(C, A0, A1, A2, A3, B0, B1) \
    asm volatile("mma.sync.aligned.m16n8k16.row.col.f32.f16.f16.f32 " \
        "{%0,%1,%2,%3}, {%4,%5,%6,%7}, {%8,%9}, {%0,%1,%2,%3};" \
        : "+f"((C)[0]), "+f"((C)[1]), "+f"((C)[2]), "+f"((C)[3]) \
        : "r"(A0), "r"(A1), "r"(A2), "r"(A3), "r"(B0), "r"(B1))
#define CP16(sm_addr, gptr) \
    asm volatile("cp.async.cg.shared.global [%0], [%1], 16;" :: "r"(sm_addr), "l"(gptr))
#define CP_COMMIT() asm volatile("cp.async.commit_group;")
#define CP_WAIT0()  asm volatile("cp.async.wait_group 0;")

// ================= K1: degree histogram (g_deg pre-zeroed) ===============
__global__ void k_hist(const int* __restrict__ dst) {
    int e = blockIdx.x * blockDim.x + threadIdx.x;
    if (e < N_EDGE) atomicAdd(&g_deg[dst[e]], 1);
}

// ================= K2: parallel CSR allocation + W^T fp16 prep ===========
// Block-local exclusive scan of degrees; one atomicAdd claims the segment.
// Segment placement across blocks is arbitrary (CSR only needs per-node
// contiguity). Also converts the three W matrices (independent work).
__global__ void __launch_bounds__(256)
k_alloc(const float* __restrict__ we, const float* __restrict__ wn,
        const float* __restrict__ wc) {
    int t = threadIdx.x;
    int i = blockIdx.x * 256 + t;

    // --- W^T -> fp16 (i < 49152) ---
    if (i < 3 * H * H) {
        int l = i >> 14, r = i & 16383;
        int k = r >> 7, h = r & 127;
        const float* W = (l == 0) ? we : (l == 1) ? wn : wc;
        g_wt[l][h * H + k] = __float2half(W[k * H + h]);
    }

    // --- node offset allocation ---
    int d = (i < N_ENT) ? g_deg[i] : 0;
    int lane = t & 31, wid = t >> 5;
    int x = d;
    #pragma unroll
    for (int o = 1; o < 32; o <<= 1) {
        int y = __shfl_up_sync(0xffffffffu, x, o);
        if (lane >= o) x += y;
    }
    __shared__ int wsum[8];
    __shared__ int blockbase;
    if (lane == 31) wsum[wid] = x;
    __syncthreads();
    if (t == 0) {
        int run = 0;
        #pragma unroll
        for (int k = 0; k < 8; k++) { int v = wsum[k]; wsum[k] = run; run += v; }
        blockbase = atomicAdd(&g_base, run);
    }
    __syncthreads();
    if (i < N_ENT) {
        int excl = blockbase + wsum[wid] + (x - d);
        g_off[i] = excl;
        g_cur[i] = excl;
    }
}

// ================= K3: dst-grouped edge lists =================
__global__ void k_fill(const int* __restrict__ src, const int* __restrict__ dst,
                       const int* __restrict__ rid) {
    int e = blockIdx.x * blockDim.x + threadIdx.x;
    if (e >= N_EDGE) return;
    int p = atomicAdd(&g_cur[dst[e]], 1);
    g_pk[p] = (unsigned)src[e] * 512u + (unsigned)rid[e];
}

// ================= K4: warp-per-node fused agg (pk software-pipelined) ====
__global__ void __launch_bounds__(256)
k_agg(const float* __restrict__ ent, const float* __restrict__ rel) {
    int w    = (blockIdx.x * blockDim.x + threadIdx.x) >> 5;
    int lane = threadIdx.x & 31;
    if (w >= N_ENT) return;

    float4 v = ((const float4*)(ent + (size_t)w * H))[lane];
    int start = g_off[w];
    int end   = start + g_deg[w];

    float4 a0 = make_float4(0.f, 0.f, 0.f, 0.f), a1 = a0, a2 = a0;
    float s0 = 0.f, s1 = 0.f, s2 = 0.f;

    unsigned nA = 0, nB = 0;
    if (start < end) {
        nA = g_pk[start];
        nB = (start + 1 < end) ? g_pk[start + 1] : nA;
    }
    for (int i = start; i < end; i += 2) {
        unsigned pA = nA, pB = nB;
        int hasB = (i + 1 < end);
        int j = i + 2;
        if (j < end) {
            nA = g_pk[j];
            nB = (j + 1 < end) ? g_pk[j + 1] : nA;
        }

        float4 uA = ((const float4*)(ent + (size_t)(pA >> 9) * H))[lane];
        float4 qA = ((const float4*)(rel + (size_t)(pA & 511u) * H))[lane];
        float4 uB = ((const float4*)(ent + (size_t)(pB >> 9) * H))[lane];
        float4 qB = ((const float4*)(rel + (size_t)(pB & 511u) * H))[lane];

        float dnA = dot4(uA, v), deA = dot4(qA, v);
        float dnB = dot4(uB, v), deB = dot4(qB, v);
        #pragma unroll
        for (int o = 16; o; o >>= 1) {
            dnA += __shfl_xor_sync(0xffffffffu, dnA, o);
            deA += __shfl_xor_sync(0xffffffffu, deA, o);
            dnB += __shfl_xor_sync(0xffffffffu, dnB, o);
            deB += __shfl_xor_sync(0xffffffffu, deB, o);
        }
        float eA = __expf(deA), nAx = __expf(dnA), cA = eA * nAx;
        s0 += eA; s1 += nAx; s2 += cA;
        a0.x += eA * qA.x; a0.y += eA * qA.y; a0.z += eA * qA.z; a0.w += eA * qA.w;
        a1.x += nAx * uA.x; a1.y += nAx * uA.y; a1.z += nAx * uA.z; a1.w += nAx * uA.w;
        a2.x += cA * (uA.x + qA.x); a2.y += cA * (uA.y + qA.y);
        a2.z += cA * (uA.z + qA.z); a2.w += cA * (uA.w + qA.w);
        if (hasB) {
            float eB = __expf(deB), nBx = __expf(dnB), cB = eB * nBx;
            s0 += eB; s1 += nBx; s2 += cB;
            a0.x += eB * qB.x; a0.y += eB * qB.y; a0.z += eB * qB.z; a0.w += eB * qB.w;
            a1.x += nBx * uB.x; a1.y += nBx * uB.y; a1.z += nBx * uB.z; a1.w += nBx * uB.w;
            a2.x += cB * (uB.x + qB.x); a2.y += cB * (uB.y + qB.y);
            a2.z += cB * (uB.z + qB.z); a2.w += cB * (uB.w + qB.w);
        }
    }

    float i0 = (end > start) ? 1.f / s0 : 0.f;
    float i1 = (end > start) ? 1.f / s1 : 0.f;
    float i2 = (end > start) ? 1.f / s2 : 0.f;
    size_t off = (size_t)w * H + lane * 4;
    *(__half2*)&g_a[0][off]     = __floats2half2_rn(a0.x * i0, a0.y * i0);
    *(__half2*)&g_a[0][off + 2] = __floats2half2_rn(a0.z * i0, a0.w * i0);
    *(__half2*)&g_a[1][off]     = __floats2half2_rn(a1.x * i1, a1.y * i1);
    *(__half2*)&g_a[1][off + 2] = __floats2half2_rn(a1.z * i1, a1.w * i1);
    *(__half2*)&g_a[2][off]     = __floats2half2_rn(a2.x * i2, a2.y * i2);
    *(__half2*)&g_a[2][off + 2] = __floats2half2_rn(a2.z * i2, a2.w * i2);
}

// ================= K5: fp16 HMMA GEMM, A double-buffered via cp.async =====
// smem: A0, A1, W (each 128 rows x 272B) = 102 KB -> 2 CTA/SM.
// Next layer's A streams during current layer's MMA loop.
#define PITCH    272
#define TILE_B   (128 * PITCH)          // 34816
#define SM_A0    0
#define SM_A1    TILE_B
#define SM_W     (2 * TILE_B)
#define SM_TOT   (3 * TILE_B)           // 104448

__device__ __forceinline__ void fill_tile_async(uint32_t smbase, const uint4* src, int tid) {
    #pragma unroll
    for (int i = 0; i < 8; i++) {
        int idx = i * 256 + tid;
        int row = idx >> 4, ch = idx & 15;
        CP16(smbase + (uint32_t)(row * PITCH + ch * 16), src + idx);
    }
}

__global__ void __launch_bounds__(256, 2)
k_gemm3(const float* __restrict__ ent, float* __restrict__ out) {
    extern __shared__ char sm[];
    uint32_t sb = smem_u32(sm);
    int tid  = threadIdx.x;
    int wid  = tid >> 5;
    int lane = tid & 31;
    int row0 = blockIdx.x * 128;

    // re-zero scratch for next graph replay (g_deg dead after k_agg)
    int z = blockIdx.x * 256 + tid;
    if (z < N_ENT) g_deg[z] = 0;
    if (z == N_ENT) g_base = 0;

    int q = lane >> 3, r = lane & 7;
    uint32_t a_off = (uint32_t)((wid * 16 + r + (q & 1) * 8) * PITCH + (q >> 1) * 16);
    uint32_t b_off = (uint32_t)(((q >> 1) * 8 + r) * PITCH + (q & 1) * 16);

    // prologue: A(0) -> buf0, W(0) -> W
    fill_tile_async(sb + SM_A0, (const uint4*)(g_a[0] + (size_t)row0 * H), tid);
    fill_tile_async(sb + SM_W,  (const uint4*)(g_wt[0]), tid);
    CP_COMMIT();
    CP_WAIT0();
    __syncthreads();

    int cur = 0;
    for (int layer = 0; layer < 3; layer++) {
        // prefetch next layer's A into the other buffer (overlaps MMA loop)
        if (layer < 2) {
            fill_tile_async(sb + (cur ? SM_A0 : SM_A1),
                            (const uint4*)(g_a[layer + 1] + (size_t)row0 * H), tid);
            CP_COMMIT();
        }

        float c[16][4];
        #pragma unroll
        for (int nt = 0; nt < 16; nt++)
            #pragma unroll
            for (int j = 0; j < 4; j++) c[nt][j] = 0.f;

        uint32_t ab = sb + (cur ? SM_A1 : SM_A0) + a_off;
        uint32_t bb = sb + SM_W + b_off;
        #pragma unroll
        for (int ks = 0; ks < 8; ks++) {
            uint32_t aa0, aa1, aa2, aa3;
            LDSM4(aa0, aa1, aa2, aa3, ab + ks * 32);
            #pragma unroll
            for (int np = 0; np < 8; np++) {
                uint32_t b0, b1, b2, b3;
                LDSM4(b0, b1, b2, b3, bb + np * (16 * PITCH) + ks * 32);
                MMA16816(c[np * 2],     aa0, aa1, aa2, aa3, b0, b1);
                MMA16816(c[np * 2 + 1], aa0, aa1, aa2, aa3, b2, b3);
            }
        }

        // epilogue: layer0 seeds with ent (replaces init copy); CTA owns rows
        int m0 = row0 + wid * 16 + (lane >> 2);
        int nb = (lane & 3) * 2;
        #pragma unroll
        for (int nt = 0; nt < 16; nt++) {
            int n = nt * 8 + nb;
            if (m0 < N_ENT) {
                float2* p = (float2*)(out + (size_t)m0 * H + n);
                float2 v0 = (layer == 0)
                    ? *(const float2*)(ent + (size_t)m0 * H + n) : *p;
                v0.x += fast_tanh(c[nt][0]);
                v0.y += fast_tanh(c[nt][1]);
                *p = v0;
            }
            if (m0 + 8 < N_ENT) {
                float2* p = (float2*)(out + (size_t)(m0 + 8) * H + n);
                float2 v1 = (layer == 0)
                    ? *(const float2*)(ent + (size_t)(m0 + 8) * H + n) : *p;
                v1.x += fast_tanh(c[nt][2]);
                v1.y += fast_tanh(c[nt][3]);
                *p = v1;
            }
        }
        __syncthreads();                 // all reads of W done
        if (layer < 2) {
            fill_tile_async(sb + SM_W, (const uint4*)(g_wt[layer + 1]), tid);
            CP_COMMIT();
            CP_WAIT0();                  // waits W(next) and A(next)
            __syncthreads();
            cur ^= 1;
        }
    }
}

// ================= launch =================
extern "C" void kernel_launch(void* const* d_in, const int* in_sizes, int n_in,
                              void* d_out, int out_size) {
    const float* ent    = (const float*)d_in[0];
    const float* rel    = (const float*)d_in[1];
    const float* w_edge = (const float*)d_in[2];
    const float* w_node = (const float*)d_in[3];
    const float* w_comp = (const float*)d_in[4];
    const int*   src    = (const int*)d_in[5];
    const int*   dst    = (const int*)d_in[6];
    const int*   rid    = (const int*)d_in[7];
    float*       out    = (float*)d_out;

    cudaFuncSetAttribute(k_gemm3, cudaFuncAttributeMaxDynamicSharedMemorySize, SM_TOT);

    // g_deg/g_base are zero at load and re-zeroed by k_gemm3 every call.
    k_hist <<<(N_EDGE + 255) / 256, 256>>>(dst);             // launch 1
    k_alloc<<<196, 256>>>(w_edge, w_node, w_comp);           // launch 2
    k_fill <<<(N_EDGE + 255) / 256, 256>>>(src, dst, rid);   // launch 3
    k_agg  <<<N_ENT / 8, 256>>>(ent, rel);                   // launch 4 <- profiled
    k_gemm3<<<N_PAD / 128, 256, SM_TOT>>>(ent, out);         // launch 5
}